// round 1
// baseline (speedup 1.0000x reference)
#include <cuda_runtime.h>
#include <math.h>

#define TOKENS 4096
#define EMB    768
#define NLAYER 12
#define NHEAD  12
#define HDIM   64
#define SEQ    1024
#define NBATCH 4
#define VOCAB  50257
#define FFDIM  3072
#define QKVDIM 2304

// -------------------- scratch (static device globals; no allocation) --------
__device__ float g_x  [TOKENS * EMB];     // residual stream
__device__ float g_a  [TOKENS * EMB];     // layernorm output
__device__ float g_qkv[TOKENS * QKVDIM];  // qkv projection
__device__ float g_y  [TOKENS * EMB];     // attention output
__device__ float g_m  [TOKENS * FFDIM];   // mlp hidden

// ---------------------------------------------------------------- embedding
__global__ void embed_kernel(const int* __restrict__ tok,
                             const float* __restrict__ wte,
                             const float* __restrict__ wpe,
                             float* __restrict__ x) {
    int idx = blockIdx.x * blockDim.x + threadIdx.x;
    if (idx >= TOKENS * EMB) return;
    int t = idx / EMB;
    int e = idx - t * EMB;
    // faithful to reference: only wpe[0] is broadcast to all positions
    x[idx] = wte[(size_t)tok[t] * EMB + e] + wpe[e];
}

// ---------------------------------------------------------------- layernorm
__global__ void ln_kernel(const float* __restrict__ x,
                          const float* __restrict__ w,
                          const float* __restrict__ bb,
                          float* __restrict__ o) {
    int row = blockIdx.x;
    const float* xr = x + (size_t)row * EMB;
    int t = threadIdx.x;
    float v0 = xr[t], v1 = xr[t + 256], v2 = xr[t + 512];
    float s  = v0 + v1 + v2;
    float sq = v0 * v0 + v1 * v1 + v2 * v2;
    #pragma unroll
    for (int off = 16; off; off >>= 1) {
        s  += __shfl_xor_sync(0xffffffffu, s, off);
        sq += __shfl_xor_sync(0xffffffffu, sq, off);
    }
    __shared__ float rs[8], rq[8];
    __shared__ float s_mean, s_rstd;
    int wid = t >> 5;
    if ((t & 31) == 0) { rs[wid] = s; rq[wid] = sq; }
    __syncthreads();
    if (t == 0) {
        float S = 0.f, Q = 0.f;
        #pragma unroll
        for (int i = 0; i < 8; i++) { S += rs[i]; Q += rq[i]; }
        float mean = S * (1.f / EMB);
        s_mean = mean;
        s_rstd = rsqrtf(Q * (1.f / EMB) - mean * mean + 1e-5f);
    }
    __syncthreads();
    float mean = s_mean, rstd = s_rstd;
    float* orow = o + (size_t)row * EMB;
    orow[t]       = (v0 - mean) * rstd * w[t]       + bb[t];
    orow[t + 256] = (v1 - mean) * rstd * w[t + 256] + bb[t + 256];
    orow[t + 512] = (v2 - mean) * rstd * w[t + 512] + bb[t + 512];
}

// --------------------------------------------------------------------- gelu
__device__ __forceinline__ float gelu_f(float x) {
    float x3 = x * x * x;
    return 0.5f * x * (1.f + tanhf(0.7978845608028654f * (x + 0.044715f * x3)));
}

// --------------------------------------------------------------------- GEMM
// C[M,N] = A[M,K] @ B  (+bias / +residual / gelu per EPI)
// TB=false: B is [K,N] row-major.  TB=true: B is [N,K] row-major (C = A @ B^T)
// EPI: 0 = +bias, 1 = +bias+residual, 2 = +bias then gelu, 3 = plain
// Tiles: 128x128x8, 256 threads, 8x8 microtile per thread.
template <int EPI, bool TB>
__global__ void __launch_bounds__(256, 2)
gemm_kernel(const float* __restrict__ A, const float* __restrict__ B,
            const float* __restrict__ bias, const float* __restrict__ res,
            float* __restrict__ C, int M, int N, int K) {
    __shared__ float sA[8][132];
    __shared__ float sB[8][132];

    const int bm = blockIdx.y * 128;
    const int bn = blockIdx.x * 128;
    const int t  = threadIdx.x;
    const int tm = (t >> 4) << 3;   // 0..120 step 8
    const int tn = (t & 15) << 3;

    float acc[8][8];
    #pragma unroll
    for (int i = 0; i < 8; i++)
        #pragma unroll
        for (int j = 0; j < 8; j++) acc[i][j] = 0.f;

    const int ar = t >> 1;          // A tile row 0..127
    const int ac = (t & 1) << 2;    // A tile col4 0 or 4

    for (int k0 = 0; k0 < K; k0 += 8) {
        // ---- load A tile (transposed store into sA[k][m]) ----
        float4 av = *(const float4*)(A + (size_t)(bm + ar) * K + k0 + ac);
        sA[ac + 0][ar] = av.x; sA[ac + 1][ar] = av.y;
        sA[ac + 2][ar] = av.z; sA[ac + 3][ar] = av.w;

        // ---- load B tile ----
        if (!TB) {
            const int bk = t >> 5;           // 0..7
            const int bc = (t & 31) << 2;    // 0..124
            float4 bv;
            const float* bp = B + (size_t)(k0 + bk) * N + bn + bc;
            if (bn + 128 <= N) {
                bv = *(const float4*)bp;
            } else {
                bv.x = (bn + bc + 0 < N) ? bp[0] : 0.f;
                bv.y = (bn + bc + 1 < N) ? bp[1] : 0.f;
                bv.z = (bn + bc + 2 < N) ? bp[2] : 0.f;
                bv.w = (bn + bc + 3 < N) ? bp[3] : 0.f;
            }
            *(float4*)&sB[bk][bc] = bv;
        } else {
            const int bnr = t >> 1;          // 0..127 (tile n)
            const int bkk = (t & 1) << 2;    // 0 or 4
            float4 bv = make_float4(0.f, 0.f, 0.f, 0.f);
            if (bn + bnr < N)
                bv = *(const float4*)(B + (size_t)(bn + bnr) * K + k0 + bkk);
            sB[bkk + 0][bnr] = bv.x; sB[bkk + 1][bnr] = bv.y;
            sB[bkk + 2][bnr] = bv.z; sB[bkk + 3][bnr] = bv.w;
        }
        __syncthreads();

        #pragma unroll
        for (int k = 0; k < 8; k++) {
            float4 a0 = *(const float4*)&sA[k][tm];
            float4 a1 = *(const float4*)&sA[k][tm + 4];
            float4 b0 = *(const float4*)&sB[k][tn];
            float4 b1 = *(const float4*)&sB[k][tn + 4];
            float ax[8] = {a0.x, a0.y, a0.z, a0.w, a1.x, a1.y, a1.z, a1.w};
            float bx[8] = {b0.x, b0.y, b0.z, b0.w, b1.x, b1.y, b1.z, b1.w};
            #pragma unroll
            for (int i = 0; i < 8; i++)
                #pragma unroll
                for (int j = 0; j < 8; j++)
                    acc[i][j] += ax[i] * bx[j];
        }
        __syncthreads();
    }

    // ---- epilogue ----
    #pragma unroll
    for (int i = 0; i < 8; i++) {
        int mi = bm + tm + i;
        #pragma unroll
        for (int j = 0; j < 8; j++) {
            int nj = bn + tn + j;
            if (nj < N) {
                float v = acc[i][j];
                if (EPI != 3) v += bias[nj];
                if (EPI == 1) v += res[(size_t)mi * N + nj];
                if (EPI == 2) v = gelu_f(v);
                C[(size_t)mi * N + nj] = v;
            }
        }
    }
}

// ---------------------------------------------------- fused flash attention
// One block per (q-tile of 64 rows, head, batch). 256 threads.
// Online softmax, 4x4 microtile per thread, causal masking.
#define AP 68   // smem pitch (floats)
__global__ void __launch_bounds__(256)
attn_kernel(const float* __restrict__ qkv, float* __restrict__ y) {
    extern __shared__ float sm[];
    float* sQT = sm;               // [64][AP]  sQT[k][r]
    float* sKT = sm + 64 * AP;     // [64][AP]  sKT[k][c]
    float* sV  = sm + 2 * 64 * AP; // [64][AP]  sV[c][d]
    float* sS  = sm + 3 * 64 * AP; // [64][AP]  sS[r][c]

    const int tq = blockIdx.x, h = blockIdx.y, b = blockIdx.z;
    const int t  = threadIdx.x;
    const int r0 = (t >> 4) << 2;   // 4 rows per thread
    const int c0 = (t & 15) << 2;   // 4 cols per thread (also d0 in PV)
    const float scale = 0.036084391824351615f;  // 1/sqrt(768)

    // ---- load Q tile (transposed) ----
    const size_t qbase = ((size_t)b * SEQ + (size_t)tq * 64) * QKVDIM + h * HDIM;
    #pragma unroll
    for (int it = 0; it < 4; it++) {
        int i   = t + it * 256;
        int row = (i >> 2) & 63;
        int kq  = (i & 3) | ((i >> 8) << 2);
        float4 v = *(const float4*)(qkv + qbase + (size_t)row * QKVDIM + kq * 4);
        int kk = kq * 4;
        sQT[(kk + 0) * AP + row] = v.x; sQT[(kk + 1) * AP + row] = v.y;
        sQT[(kk + 2) * AP + row] = v.z; sQT[(kk + 3) * AP + row] = v.w;
    }

    float m[4], l[4], acc[4][4];
    #pragma unroll
    for (int i = 0; i < 4; i++) {
        m[i] = -1e30f; l[i] = 0.f;
        #pragma unroll
        for (int j = 0; j < 4; j++) acc[i][j] = 0.f;
    }

    for (int ks = 0; ks <= tq; ks++) {
        __syncthreads();  // prev PV done; Q stores visible on first pass
        const size_t kbase = ((size_t)b * SEQ + (size_t)ks * 64) * QKVDIM + h * HDIM + EMB;
        #pragma unroll
        for (int it = 0; it < 4; it++) {
            int i   = t + it * 256;
            int row = (i >> 2) & 63;
            int kq  = (i & 3) | ((i >> 8) << 2);
            float4 kv = *(const float4*)(qkv + kbase + (size_t)row * QKVDIM + kq * 4);
            float4 vv = *(const float4*)(qkv + kbase + EMB + (size_t)row * QKVDIM + kq * 4);
            int kk = kq * 4;
            sKT[(kk + 0) * AP + row] = kv.x; sKT[(kk + 1) * AP + row] = kv.y;
            sKT[(kk + 2) * AP + row] = kv.z; sKT[(kk + 3) * AP + row] = kv.w;
            *(float4*)&sV[row * AP + kk] = vv;
        }
        __syncthreads();

        // ---- scores S = Q K^T (64x64x64) ----
        float sc[4][4];
        #pragma unroll
        for (int i = 0; i < 4; i++)
            #pragma unroll
            for (int j = 0; j < 4; j++) sc[i][j] = 0.f;

        #pragma unroll 16
        for (int k = 0; k < 64; k++) {
            float4 qv = *(const float4*)&sQT[k * AP + r0];
            float4 kv = *(const float4*)&sKT[k * AP + c0];
            float qa[4] = {qv.x, qv.y, qv.z, qv.w};
            float ka[4] = {kv.x, kv.y, kv.z, kv.w};
            #pragma unroll
            for (int i = 0; i < 4; i++)
                #pragma unroll
                for (int j = 0; j < 4; j++)
                    sc[i][j] += qa[i] * ka[j];
        }

        const bool diag = (ks == tq);
        #pragma unroll
        for (int i = 0; i < 4; i++) {
            #pragma unroll
            for (int j = 0; j < 4; j++) {
                float v = sc[i][j] * scale;
                if (diag && (c0 + j > r0 + i)) v = -1e30f;
                sc[i][j] = v;
            }
        }

        // ---- online softmax update (row groups of 16 threads) ----
        #pragma unroll
        for (int i = 0; i < 4; i++) {
            float tmax = fmaxf(fmaxf(sc[i][0], sc[i][1]), fmaxf(sc[i][2], sc[i][3]));
            #pragma unroll
            for (int off = 1; off < 16; off <<= 1)
                tmax = fmaxf(tmax, __shfl_xor_sync(0xffffffffu, tmax, off));
            float nm   = fmaxf(m[i], tmax);
            float corr = __expf(m[i] - nm);
            m[i] = nm;
            float rs = 0.f;
            #pragma unroll
            for (int j = 0; j < 4; j++) {
                float p = __expf(sc[i][j] - nm);
                sc[i][j] = p;
                rs += p;
            }
            #pragma unroll
            for (int off = 1; off < 16; off <<= 1)
                rs += __shfl_xor_sync(0xffffffffu, rs, off);
            l[i] = l[i] * corr + rs;
            acc[i][0] *= corr; acc[i][1] *= corr;
            acc[i][2] *= corr; acc[i][3] *= corr;
            *(float4*)&sS[(r0 + i) * AP + c0] =
                make_float4(sc[i][0], sc[i][1], sc[i][2], sc[i][3]);
        }
        __syncthreads();

        // ---- PV: acc += P @ V ----
        #pragma unroll 8
        for (int c = 0; c < 64; c++) {
            float4 v = *(const float4*)&sV[c * AP + c0];
            #pragma unroll
            for (int i = 0; i < 4; i++) {
                float p = sS[(r0 + i) * AP + c];
                acc[i][0] += p * v.x; acc[i][1] += p * v.y;
                acc[i][2] += p * v.z; acc[i][3] += p * v.w;
            }
        }
    }

    // ---- write output (back to [token, E] layout) ----
    #pragma unroll
    for (int i = 0; i < 4; i++) {
        float inv = 1.f / l[i];
        float4 o = make_float4(acc[i][0] * inv, acc[i][1] * inv,
                               acc[i][2] * inv, acc[i][3] * inv);
        *(float4*)(y + ((size_t)b * SEQ + (size_t)tq * 64 + r0 + i) * EMB
                     + h * HDIM + c0) = o;
    }
}

// -------------------------------------------------------------------- launch
extern "C" void kernel_launch(void* const* d_in, const int* in_sizes, int n_in,
                              void* d_out, int out_size) {
    const int*   tokens = (const int*)  d_in[0];
    const float* wte    = (const float*)d_in[1];
    const float* wpe    = (const float*)d_in[2];
    const float* ln1w   = (const float*)d_in[3];
    const float* ln1b   = (const float*)d_in[4];
    const float* qkvw   = (const float*)d_in[5];
    const float* qkvb   = (const float*)d_in[6];
    const float* atpw   = (const float*)d_in[7];
    const float* atpb   = (const float*)d_in[8];
    const float* ln2w   = (const float*)d_in[9];
    const float* ln2b   = (const float*)d_in[10];
    const float* fcw    = (const float*)d_in[11];
    const float* fcb    = (const float*)d_in[12];
    const float* fpw    = (const float*)d_in[13];
    const float* fpb    = (const float*)d_in[14];
    const float* lnfw   = (const float*)d_in[15];
    const float* lnfb   = (const float*)d_in[16];
    const float* lmw    = (const float*)d_in[17];
    float* out = (float*)d_out;

    float *px, *pa, *pqkv, *py, *pm;
    cudaGetSymbolAddress((void**)&px,   g_x);
    cudaGetSymbolAddress((void**)&pa,   g_a);
    cudaGetSymbolAddress((void**)&pqkv, g_qkv);
    cudaGetSymbolAddress((void**)&py,   g_y);
    cudaGetSymbolAddress((void**)&pm,   g_m);

    const size_t attn_smem = (size_t)4 * 64 * AP * sizeof(float);  // ~68 KB
    cudaFuncSetAttribute(attn_kernel,
                         cudaFuncAttributeMaxDynamicSharedMemorySize,
                         (int)attn_smem);

    embed_kernel<<<(TOKENS * EMB + 255) / 256, 256>>>(tokens, wte, wpe, px);

    for (int i = 0; i < NLAYER; i++) {
        ln_kernel<<<TOKENS, 256>>>(px, ln1w + i * EMB, ln1b + i * EMB, pa);

        gemm_kernel<0, false><<<dim3(QKVDIM / 128, TOKENS / 128), 256>>>(
            pa, qkvw + (size_t)i * EMB * QKVDIM, qkvb + i * QKVDIM,
            nullptr, pqkv, TOKENS, QKVDIM, EMB);

        attn_kernel<<<dim3(SEQ / 64, NHEAD, NBATCH), 256, attn_smem>>>(pqkv, py);

        gemm_kernel<1, false><<<dim3(EMB / 128, TOKENS / 128), 256>>>(
            py, atpw + (size_t)i * EMB * EMB, atpb + i * EMB,
            px, px, TOKENS, EMB, EMB);

        ln_kernel<<<TOKENS, 256>>>(px, ln2w + i * EMB, ln2b + i * EMB, pa);

        gemm_kernel<2, false><<<dim3(FFDIM / 128, TOKENS / 128), 256>>>(
            pa, fcw + (size_t)i * EMB * FFDIM, fcb + i * FFDIM,
            nullptr, pm, TOKENS, FFDIM, EMB);

        gemm_kernel<1, false><<<dim3(EMB / 128, TOKENS / 128), 256>>>(
            pm, fpw + (size_t)i * FFDIM * EMB, fpb + i * EMB,
            px, px, TOKENS, EMB, FFDIM);
    }

    ln_kernel<<<TOKENS, 256>>>(px, lnfw, lnfb, pa);

    gemm_kernel<3, true><<<dim3((VOCAB + 127) / 128, TOKENS / 128), 256>>>(
        pa, lmw, nullptr, nullptr, out, TOKENS, VOCAB, EMB);
}

// round 3
// speedup vs baseline: 2.2855x; 2.2855x over previous
#include <cuda_runtime.h>
#include <math.h>
#include <stdint.h>

#define TOKENS 4096
#define EMB    768
#define NLAYER 12
#define NHEAD  12
#define HDIM   64
#define SEQ    1024
#define NBATCH 4
#define VOCAB  50257
#define FFDIM  3072
#define QKVDIM 2304

// -------------------- scratch (static device globals; no allocation) --------
__device__ float g_x  [TOKENS * EMB];
__device__ float g_a  [TOKENS * EMB];
__device__ float g_qkv[TOKENS * QKVDIM];
__device__ float g_y  [TOKENS * EMB];
__device__ float g_m  [TOKENS * FFDIM];
// transposed weights ([N,K] K-major: B operand for C = A @ B^T)
__device__ float g_qkvT[(size_t)NLAYER * QKVDIM * EMB];
__device__ float g_atpT[(size_t)NLAYER * EMB * EMB];
__device__ float g_fcT [(size_t)NLAYER * FFDIM * EMB];
__device__ float g_fpT [(size_t)NLAYER * EMB * FFDIM];

// ------------------------------------------------------------- helpers
__device__ __forceinline__ uint32_t tf32r(float x) {
    uint32_t r;
    asm("cvt.rna.tf32.f32 %0, %1;" : "=r"(r) : "f"(x));
    return r;
}
__device__ __forceinline__ float gelu_f(float x) {
    float x3 = x * x * x;
    return 0.5f * x * (1.f + tanhf(0.7978845608028654f * (x + 0.044715f * x3)));
}
__device__ __forceinline__ void mma_tf32(float* c, const uint32_t* a, const uint32_t* b) {
    asm volatile(
        "mma.sync.aligned.m16n8k8.row.col.f32.tf32.tf32.f32 "
        "{%0,%1,%2,%3}, {%4,%5,%6,%7}, {%8,%9}, {%0,%1,%2,%3};"
        : "+f"(c[0]), "+f"(c[1]), "+f"(c[2]), "+f"(c[3])
        : "r"(a[0]), "r"(a[1]), "r"(a[2]), "r"(a[3]), "r"(b[0]), "r"(b[1]));
}

// ---------------------------------------------------------------- embedding
__global__ void embed_kernel(const int* __restrict__ tok,
                             const float* __restrict__ wte,
                             const float* __restrict__ wpe,
                             float* __restrict__ x) {
    int idx = blockIdx.x * blockDim.x + threadIdx.x;
    if (idx >= TOKENS * EMB) return;
    int t = idx / EMB;
    int e = idx - t * EMB;
    x[idx] = wte[(size_t)tok[t] * EMB + e] + wpe[e];
}

// ---------------------------------------------------------------- layernorm
__global__ void ln_kernel(const float* __restrict__ x,
                          const float* __restrict__ w,
                          const float* __restrict__ bb,
                          float* __restrict__ o) {
    int row = blockIdx.x;
    const float* xr = x + (size_t)row * EMB;
    int t = threadIdx.x;
    float v0 = xr[t], v1 = xr[t + 256], v2 = xr[t + 512];
    float s  = v0 + v1 + v2;
    float sq = v0 * v0 + v1 * v1 + v2 * v2;
    #pragma unroll
    for (int off = 16; off; off >>= 1) {
        s  += __shfl_xor_sync(0xffffffffu, s, off);
        sq += __shfl_xor_sync(0xffffffffu, sq, off);
    }
    __shared__ float rs[8], rq[8];
    __shared__ float s_mean, s_rstd;
    int wid = t >> 5;
    if ((t & 31) == 0) { rs[wid] = s; rq[wid] = sq; }
    __syncthreads();
    if (t == 0) {
        float S = 0.f, Q = 0.f;
        #pragma unroll
        for (int i = 0; i < 8; i++) { S += rs[i]; Q += rq[i]; }
        float mean = S * (1.f / EMB);
        s_mean = mean;
        s_rstd = rsqrtf(Q * (1.f / EMB) - mean * mean + 1e-5f);
    }
    __syncthreads();
    float mean = s_mean, rstd = s_rstd;
    float* orow = o + (size_t)row * EMB;
    orow[t]       = (v0 - mean) * rstd * w[t]       + bb[t];
    orow[t + 256] = (v1 - mean) * rstd * w[t + 256] + bb[t + 256];
    orow[t + 512] = (v2 - mean) * rstd * w[t + 512] + bb[t + 512];
}

// ---------------------------------------------------------------- transpose
__global__ void transpose_kernel(const float* __restrict__ in,
                                 float* __restrict__ out, int K, int N) {
    __shared__ float t[32][33];
    const size_t off = (size_t)blockIdx.z * K * N;
    int n0 = blockIdx.x * 32, k0 = blockIdx.y * 32;
    int x = threadIdx.x, y = threadIdx.y;
    #pragma unroll
    for (int i = 0; i < 32; i += 8)
        t[y + i][x] = in[off + (size_t)(k0 + y + i) * N + n0 + x];
    __syncthreads();
    #pragma unroll
    for (int i = 0; i < 32; i += 8)
        out[off + (size_t)(n0 + y + i) * K + k0 + x] = t[x][y + i];
}

// ------------------------------------------------------ tf32 mma.sync GEMM
// C[M,N] = A[M,K] @ Bt[N,K]^T   (Bt rows are output columns, K-major)
// EPI: 0 = +bias, 1 = +bias+residual, 2 = +bias+gelu, 3 = plain (N guarded)
// CTA tile 128x128x32; 8 warps as 2(m) x 4(n); warp tile 64x32.
#define PITCH 36
template <int EPI>
__global__ void __launch_bounds__(256)
gemm_mma(const float* __restrict__ A, const float* __restrict__ Bt,
         const float* __restrict__ bias, const float* __restrict__ res,
         float* __restrict__ C, int M, int N, int K) {
    extern __shared__ float sm[];
    float* sA = sm;                      // 2 x [128][PITCH]
    float* sB = sm + 2 * 128 * PITCH;    // 2 x [128][PITCH]

    const int tid  = threadIdx.x;
    const int wid  = tid >> 5;
    const int lane = tid & 31;
    const int grp  = lane >> 2;   // 0..7
    const int tig  = lane & 3;    // 0..3
    const int bm = blockIdx.y * 128;
    const int bn = blockIdx.x * 128;
    const int wm0 = (wid & 1) * 64;
    const int wn0 = (wid >> 1) * 32;

    const int srow = tid >> 3;        // staging row 0..31 per iter? no: see below
    const int squad = tid & 7;        // quad within row

    float cf[4][4][4];
    #pragma unroll
    for (int i = 0; i < 4; i++)
        #pragma unroll
        for (int j = 0; j < 4; j++)
            #pragma unroll
            for (int r = 0; r < 4; r++) cf[i][j][r] = 0.f;

    const int KC = K >> 5;   // 32-wide k chunks

    float4 av[4], bv[4];

    // ---- prologue: load + store chunk 0 ----
    #pragma unroll
    for (int it = 0; it < 4; it++) {
        int row = srow + it * 32;
        av[it] = *(const float4*)(A + (size_t)(bm + row) * K + squad * 4);
        if (EPI == 3) {
            if (bn + row < N)
                bv[it] = *(const float4*)(Bt + (size_t)(bn + row) * K + squad * 4);
            else
                bv[it] = make_float4(0.f, 0.f, 0.f, 0.f);
        } else {
            bv[it] = *(const float4*)(Bt + (size_t)(bn + row) * K + squad * 4);
        }
    }
    #pragma unroll
    for (int it = 0; it < 4; it++) {
        int row = srow + it * 32;
        uint4 ua = make_uint4(tf32r(av[it].x), tf32r(av[it].y), tf32r(av[it].z), tf32r(av[it].w));
        uint4 ub = make_uint4(tf32r(bv[it].x), tf32r(bv[it].y), tf32r(bv[it].z), tf32r(bv[it].w));
        *(uint4*)&sA[row * PITCH + squad * 4] = ua;
        *(uint4*)&sB[row * PITCH + squad * 4] = ub;
    }
    __syncthreads();

    for (int c = 0; c < KC; c++) {
        const int p = c & 1;
        const float* cA = sA + p * 128 * PITCH;
        const float* cB = sB + p * 128 * PITCH;

        // prefetch next chunk from gmem
        if (c + 1 < KC) {
            const int k0 = (c + 1) << 5;
            #pragma unroll
            for (int it = 0; it < 4; it++) {
                int row = srow + it * 32;
                av[it] = *(const float4*)(A + (size_t)(bm + row) * K + k0 + squad * 4);
                if (EPI == 3) {
                    if (bn + row < N)
                        bv[it] = *(const float4*)(Bt + (size_t)(bn + row) * K + k0 + squad * 4);
                    else
                        bv[it] = make_float4(0.f, 0.f, 0.f, 0.f);
                } else {
                    bv[it] = *(const float4*)(Bt + (size_t)(bn + row) * K + k0 + squad * 4);
                }
            }
        }

        // ---- mma over 4 k-steps of 8 ----
        #pragma unroll
        for (int ks = 0; ks < 4; ks++) {
            const int k0 = ks * 8;
            uint32_t af[4][4], bf[4][2];
            #pragma unroll
            for (int mt = 0; mt < 4; mt++) {
                const float* ap = cA + (wm0 + mt * 16 + grp) * PITCH + k0 + tig;
                af[mt][0] = __float_as_uint(ap[0]);
                af[mt][1] = __float_as_uint(ap[8 * PITCH]);
                af[mt][2] = __float_as_uint(ap[4]);
                af[mt][3] = __float_as_uint(ap[8 * PITCH + 4]);
            }
            #pragma unroll
            for (int nt = 0; nt < 4; nt++) {
                const float* bp = cB + (wn0 + nt * 8 + grp) * PITCH + k0 + tig;
                bf[nt][0] = __float_as_uint(bp[0]);
                bf[nt][1] = __float_as_uint(bp[4]);
            }
            #pragma unroll
            for (int mt = 0; mt < 4; mt++)
                #pragma unroll
                for (int nt = 0; nt < 4; nt++)
                    mma_tf32(cf[mt][nt], af[mt], bf[nt]);
        }
        __syncthreads();

        if (c + 1 < KC) {
            float* nA = sA + ((c + 1) & 1) * 128 * PITCH;
            float* nB = sB + ((c + 1) & 1) * 128 * PITCH;
            #pragma unroll
            for (int it = 0; it < 4; it++) {
                int row = srow + it * 32;
                uint4 ua = make_uint4(tf32r(av[it].x), tf32r(av[it].y), tf32r(av[it].z), tf32r(av[it].w));
                uint4 ub = make_uint4(tf32r(bv[it].x), tf32r(bv[it].y), tf32r(bv[it].z), tf32r(bv[it].w));
                *(uint4*)&nA[row * PITCH + squad * 4] = ua;
                *(uint4*)&nB[row * PITCH + squad * 4] = ub;
            }
            __syncthreads();
        }
    }

    // ---------------- epilogue ----------------
    #pragma unroll
    for (int mt = 0; mt < 4; mt++) {
        #pragma unroll
        for (int half = 0; half < 2; half++) {
            const int row = bm + wm0 + mt * 16 + grp + half * 8;
            #pragma unroll
            for (int nt = 0; nt < 4; nt++) {
                const int col = bn + wn0 + nt * 8 + 2 * tig;
                float v0 = cf[mt][nt][half * 2 + 0];
                float v1 = cf[mt][nt][half * 2 + 1];
                if (EPI == 3) {
                    if (col < N)     C[(size_t)row * N + col]     = v0;
                    if (col + 1 < N) C[(size_t)row * N + col + 1] = v1;
                } else {
                    v0 += bias[col];
                    v1 += bias[col + 1];
                    if (EPI == 1) {
                        const float* rp = res + (size_t)row * N + col;
                        v0 += rp[0]; v1 += rp[1];
                    }
                    if (EPI == 2) { v0 = gelu_f(v0); v1 = gelu_f(v1); }
                    float2 o = make_float2(v0, v1);
                    *(float2*)(C + (size_t)row * N + col) = o;
                }
            }
        }
    }
}

// ---------------------------------------------------- fused flash attention
#define AP 68
__global__ void __launch_bounds__(256)
attn_kernel(const float* __restrict__ qkv, float* __restrict__ y) {
    extern __shared__ float sm[];
    float* sQT = sm;
    float* sKT = sm + 64 * AP;
    float* sV  = sm + 2 * 64 * AP;
    float* sS  = sm + 3 * 64 * AP;

    const int tq = blockIdx.x, h = blockIdx.y, b = blockIdx.z;
    const int t  = threadIdx.x;
    const int r0 = (t >> 4) << 2;
    const int c0 = (t & 15) << 2;
    const float scale = 0.036084391824351615f;  // 1/sqrt(768)

    const size_t qbase = ((size_t)b * SEQ + (size_t)tq * 64) * QKVDIM + h * HDIM;
    #pragma unroll
    for (int it = 0; it < 4; it++) {
        int i   = t + it * 256;
        int row = (i >> 2) & 63;
        int kq  = (i & 3) | ((i >> 8) << 2);
        float4 v = *(const float4*)(qkv + qbase + (size_t)row * QKVDIM + kq * 4);
        int kk = kq * 4;
        sQT[(kk + 0) * AP + row] = v.x; sQT[(kk + 1) * AP + row] = v.y;
        sQT[(kk + 2) * AP + row] = v.z; sQT[(kk + 3) * AP + row] = v.w;
    }

    float m[4], l[4], acc[4][4];
    #pragma unroll
    for (int i = 0; i < 4; i++) {
        m[i] = -1e30f; l[i] = 0.f;
        #pragma unroll
        for (int j = 0; j < 4; j++) acc[i][j] = 0.f;
    }

    for (int ks = 0; ks <= tq; ks++) {
        __syncthreads();
        const size_t kbase = ((size_t)b * SEQ + (size_t)ks * 64) * QKVDIM + h * HDIM + EMB;
        #pragma unroll
        for (int it = 0; it < 4; it++) {
            int i   = t + it * 256;
            int row = (i >> 2) & 63;
            int kq  = (i & 3) | ((i >> 8) << 2);
            float4 kv = *(const float4*)(qkv + kbase + (size_t)row * QKVDIM + kq * 4);
            float4 vv = *(const float4*)(qkv + kbase + EMB + (size_t)row * QKVDIM + kq * 4);
            int kk = kq * 4;
            sKT[(kk + 0) * AP + row] = kv.x; sKT[(kk + 1) * AP + row] = kv.y;
            sKT[(kk + 2) * AP + row] = kv.z; sKT[(kk + 3) * AP + row] = kv.w;
            *(float4*)&sV[row * AP + kk] = vv;
        }
        __syncthreads();

        float sc[4][4];
        #pragma unroll
        for (int i = 0; i < 4; i++)
            #pragma unroll
            for (int j = 0; j < 4; j++) sc[i][j] = 0.f;

        #pragma unroll 16
        for (int k = 0; k < 64; k++) {
            float4 qv = *(const float4*)&sQT[k * AP + r0];
            float4 kv = *(const float4*)&sKT[k * AP + c0];
            float qa[4] = {qv.x, qv.y, qv.z, qv.w};
            float ka[4] = {kv.x, kv.y, kv.z, kv.w};
            #pragma unroll
            for (int i = 0; i < 4; i++)
                #pragma unroll
                for (int j = 0; j < 4; j++)
                    sc[i][j] += qa[i] * ka[j];
        }

        const bool diag = (ks == tq);
        #pragma unroll
        for (int i = 0; i < 4; i++)
            #pragma unroll
            for (int j = 0; j < 4; j++) {
                float v = sc[i][j] * scale;
                if (diag && (c0 + j > r0 + i)) v = -1e30f;
                sc[i][j] = v;
            }

        #pragma unroll
        for (int i = 0; i < 4; i++) {
            float tmax = fmaxf(fmaxf(sc[i][0], sc[i][1]), fmaxf(sc[i][2], sc[i][3]));
            #pragma unroll
            for (int off = 1; off < 16; off <<= 1)
                tmax = fmaxf(tmax, __shfl_xor_sync(0xffffffffu, tmax, off));
            float nm   = fmaxf(m[i], tmax);
            float corr = __expf(m[i] - nm);
            m[i] = nm;
            float rs = 0.f;
            #pragma unroll
            for (int j = 0; j < 4; j++) {
                float p = __expf(sc[i][j] - nm);
                sc[i][j] = p;
                rs += p;
            }
            #pragma unroll
            for (int off = 1; off < 16; off <<= 1)
                rs += __shfl_xor_sync(0xffffffffu, rs, off);
            l[i] = l[i] * corr + rs;
            acc[i][0] *= corr; acc[i][1] *= corr;
            acc[i][2] *= corr; acc[i][3] *= corr;
            *(float4*)&sS[(r0 + i) * AP + c0] =
                make_float4(sc[i][0], sc[i][1], sc[i][2], sc[i][3]);
        }
        __syncthreads();

        #pragma unroll 8
        for (int c = 0; c < 64; c++) {
            float4 v = *(const float4*)&sV[c * AP + c0];
            #pragma unroll
            for (int i = 0; i < 4; i++) {
                float p = sS[(r0 + i) * AP + c];
                acc[i][0] += p * v.x; acc[i][1] += p * v.y;
                acc[i][2] += p * v.z; acc[i][3] += p * v.w;
            }
        }
    }

    #pragma unroll
    for (int i = 0; i < 4; i++) {
        float inv = 1.f / l[i];
        float4 o = make_float4(acc[i][0] * inv, acc[i][1] * inv,
                               acc[i][2] * inv, acc[i][3] * inv);
        *(float4*)(y + ((size_t)b * SEQ + (size_t)tq * 64 + r0 + i) * EMB
                     + h * HDIM + c0) = o;
    }
}

// -------------------------------------------------------------------- launch
extern "C" void kernel_launch(void* const* d_in, const int* in_sizes, int n_in,
                              void* d_out, int out_size) {
    const int*   tokens = (const int*)  d_in[0];
    const float* wte    = (const float*)d_in[1];
    const float* wpe    = (const float*)d_in[2];
    const float* ln1w   = (const float*)d_in[3];
    const float* ln1b   = (const float*)d_in[4];
    const float* qkvw   = (const float*)d_in[5];
    const float* qkvb   = (const float*)d_in[6];
    const float* atpw   = (const float*)d_in[7];
    const float* atpb   = (const float*)d_in[8];
    const float* ln2w   = (const float*)d_in[9];
    const float* ln2b   = (const float*)d_in[10];
    const float* fcw    = (const float*)d_in[11];
    const float* fcb    = (const float*)d_in[12];
    const float* fpw    = (const float*)d_in[13];
    const float* fpb    = (const float*)d_in[14];
    const float* lnfw   = (const float*)d_in[15];
    const float* lnfb   = (const float*)d_in[16];
    const float* lmw    = (const float*)d_in[17];
    float* out = (float*)d_out;

    float *px, *pa, *pqkv, *py, *pm, *pqkvT, *patpT, *pfcT, *pfpT;
    cudaGetSymbolAddress((void**)&px,    g_x);
    cudaGetSymbolAddress((void**)&pa,    g_a);
    cudaGetSymbolAddress((void**)&pqkv,  g_qkv);
    cudaGetSymbolAddress((void**)&py,    g_y);
    cudaGetSymbolAddress((void**)&pm,    g_m);
    cudaGetSymbolAddress((void**)&pqkvT, g_qkvT);
    cudaGetSymbolAddress((void**)&patpT, g_atpT);
    cudaGetSymbolAddress((void**)&pfcT,  g_fcT);
    cudaGetSymbolAddress((void**)&pfpT,  g_fpT);

    const int gsmem = 2 * 2 * 128 * PITCH * sizeof(float);  // 73728
    cudaFuncSetAttribute(gemm_mma<0>, cudaFuncAttributeMaxDynamicSharedMemorySize, gsmem);
    cudaFuncSetAttribute(gemm_mma<1>, cudaFuncAttributeMaxDynamicSharedMemorySize, gsmem);
    cudaFuncSetAttribute(gemm_mma<2>, cudaFuncAttributeMaxDynamicSharedMemorySize, gsmem);
    cudaFuncSetAttribute(gemm_mma<3>, cudaFuncAttributeMaxDynamicSharedMemorySize, gsmem);

    const size_t attn_smem = (size_t)4 * 64 * AP * sizeof(float);
    cudaFuncSetAttribute(attn_kernel,
                         cudaFuncAttributeMaxDynamicSharedMemorySize,
                         (int)attn_smem);

    dim3 tb(32, 8);
    transpose_kernel<<<dim3(QKVDIM / 32, EMB / 32, NLAYER), tb>>>(qkvw, pqkvT, EMB, QKVDIM);
    transpose_kernel<<<dim3(EMB / 32,    EMB / 32, NLAYER), tb>>>(atpw, patpT, EMB, EMB);
    transpose_kernel<<<dim3(FFDIM / 32,  EMB / 32, NLAYER), tb>>>(fcw,  pfcT,  EMB, FFDIM);
    transpose_kernel<<<dim3(EMB / 32,  FFDIM / 32, NLAYER), tb>>>(fpw,  pfpT,  FFDIM, EMB);

    embed_kernel<<<(TOKENS * EMB + 255) / 256, 256>>>(tokens, wte, wpe, px);

    for (int i = 0; i < NLAYER; i++) {
        ln_kernel<<<TOKENS, 256>>>(px, ln1w + i * EMB, ln1b + i * EMB, pa);

        gemm_mma<0><<<dim3(QKVDIM / 128, TOKENS / 128), 256, gsmem>>>(
            pa, pqkvT + (size_t)i * QKVDIM * EMB, qkvb + i * QKVDIM,
            nullptr, pqkv, TOKENS, QKVDIM, EMB);

        attn_kernel<<<dim3(SEQ / 64, NHEAD, NBATCH), 256, attn_smem>>>(pqkv, py);

        gemm_mma<1><<<dim3(EMB / 128, TOKENS / 128), 256, gsmem>>>(
            py, patpT + (size_t)i * EMB * EMB, atpb + i * EMB,
            px, px, TOKENS, EMB, EMB);

        ln_kernel<<<TOKENS, 256>>>(px, ln2w + i * EMB, ln2b + i * EMB, pa);

        gemm_mma<2><<<dim3(FFDIM / 128, TOKENS / 128), 256, gsmem>>>(
            pa, pfcT + (size_t)i * FFDIM * EMB, fcb + i * FFDIM,
            nullptr, pm, TOKENS, FFDIM, EMB);

        gemm_mma<1><<<dim3(EMB / 128, TOKENS / 128), 256, gsmem>>>(
            pm, pfpT + (size_t)i * EMB * FFDIM, fpb + i * EMB,
            px, px, TOKENS, EMB, FFDIM);
    }

    ln_kernel<<<TOKENS, 256>>>(px, lnfw, lnfb, pa);

    gemm_mma<3><<<dim3((VOCAB + 127) / 128, TOKENS / 128), 256, gsmem>>>(
        pa, lmw, nullptr, nullptr, out, TOKENS, VOCAB, EMB);
}